// round 2
// baseline (speedup 1.0000x reference)
#include <cuda_runtime.h>
#include <cuda_bf16.h>
#include <cstdint>
#include <math.h>

#define DIM   1024
#define TOK   4096
#define MA    32768
#define NU    34
#define FDIM  4096
#define SCL   0.03125f

__device__ float g_C [(size_t)DIM*DIM];
__device__ float g_CA[(size_t)MA*DIM];
__device__ float g_G [(size_t)MA*NU];
__device__ float g_U [(size_t)NU*DIM];
__device__ float g_CB[(size_t)TOK*32];
__device__ float g_Z [(size_t)TOK*DIM];
__device__ float g_CO[(size_t)TOK*DIM];
__device__ float g_H [(size_t)TOK*FDIM];
__device__ float g_pbv[32];
__device__ float g_c0[1];

#define BM 128
#define BN 128
#define BK 32
#define SROW 40
#define TILEH (BM*SROW)
#define GEMM_SMEM (2*4*TILEH*2)

__device__ __forceinline__ void mma_bf16(float c[4], const uint32_t a[4], const uint32_t b[2]){
  asm volatile(
    "mma.sync.aligned.m16n8k16.row.col.f32.bf16.bf16.f32 "
    "{%0,%1,%2,%3}, {%4,%5,%6,%7}, {%8,%9}, {%0,%1,%2,%3};\n"
    : "+f"(c[0]), "+f"(c[1]), "+f"(c[2]), "+f"(c[3])
    : "r"(a[0]), "r"(a[1]), "r"(a[2]), "r"(a[3]), "r"(b[0]), "r"(b[1]));
}

__device__ __forceinline__ void bsplit(float v, __nv_bfloat16 &h, __nv_bfloat16 &l){
  h = __float2bfloat16_rn(v);
  l = __float2bfloat16_rn(v - __bfloat162float(h));
}

// EPI: 0 store, 1 +bias, 2 gelu(+bias), 3 +bias+X2
template<int EPI>
__device__ __forceinline__ void emit_one(float* __restrict__ C, int row, int col, int N,
                                         float v, const float* __restrict__ bias,
                                         const float* __restrict__ X2){
  if (col >= N) return;
  if (EPI==1) v += bias[col];
  else if (EPI==2){ v += bias[col]; v = 0.5f*v*(1.0f + erff(v*0.70710678f)); }
  else if (EPI==3){ v += bias[col] + X2[(size_t)row*N + col]; }
  C[(size_t)row*N + col] = v;
}

// C[m,n] = sum_k A'[m,k]*B'[n,k];  TA: A'[m,k]=A[k*M+m]; TB: B'[n,k]=B[k*N+n]
// M %128==0, K %32==0, N arbitrary.
template<bool TA, bool TB, int EPI>
__global__ __launch_bounds__(256)
void gemm_k(const float* __restrict__ A, const float* __restrict__ B,
            float* __restrict__ C, int M, int N, int K,
            const float* __restrict__ bias, const float* __restrict__ X2)
{
  extern __shared__ char dynsm[];
  __nv_bfloat16* sbase = (__nv_bfloat16*)dynsm;
  const int tid = threadIdx.x;
  const int mBase = blockIdx.y * BM;
  const int nBase = blockIdx.x * BN;

  float acc[2][8][4];
#pragma unroll
  for (int a=0;a<2;a++)
#pragma unroll
    for (int b=0;b<8;b++)
#pragma unroll
      for (int c=0;c<4;c++) acc[a][b][c]=0.f;

  float4 pa[4], pb[4];
  const int nK = K / BK;

  auto loadA = [&](int k0){
    if (!TA){
#pragma unroll
      for (int it=0; it<4; ++it){
        int id = tid + it*256, row = id>>3, c4 = id&7;
        pa[it] = *(const float4*)(A + (size_t)(mBase+row)*K + k0 + c4*4);
      }
    } else {
#pragma unroll
      for (int it=0; it<4; ++it){
        int kk = (tid>>5) + it*8, m4 = tid&31;
        pa[it] = *(const float4*)(A + (size_t)(k0+kk)*M + mBase + m4*4);
      }
    }
  };
  auto loadB = [&](int k0){
    if (!TB){
#pragma unroll
      for (int it=0; it<4; ++it){
        int id = tid + it*256, row = id>>3, c4 = id&7;
        if (nBase + row < N)
          pb[it] = *(const float4*)(B + (size_t)(nBase+row)*K + k0 + c4*4);
        else pb[it] = make_float4(0.f,0.f,0.f,0.f);
      }
    } else {
#pragma unroll
      for (int it=0; it<4; ++it){
        int kk = (tid>>5) + it*8, n4 = tid&31;
        int n0 = nBase + n4*4;
        if (n0 + 3 < N){
          pb[it] = *(const float4*)(B + (size_t)(k0+kk)*N + n0);
        } else {
          float t0 = (n0   < N) ? B[(size_t)(k0+kk)*N + n0  ] : 0.f;
          float t1 = (n0+1 < N) ? B[(size_t)(k0+kk)*N + n0+1] : 0.f;
          float t2 = (n0+2 < N) ? B[(size_t)(k0+kk)*N + n0+2] : 0.f;
          float t3 = (n0+3 < N) ? B[(size_t)(k0+kk)*N + n0+3] : 0.f;
          pb[it] = make_float4(t0,t1,t2,t3);
        }
      }
    }
  };

  auto stsAll = [&](int stage){
    __nv_bfloat16* hA = sbase + stage*4*TILEH;
    __nv_bfloat16* lA = hA + TILEH;
    __nv_bfloat16* hB = lA + TILEH;
    __nv_bfloat16* lB = hB + TILEH;
#pragma unroll
    for (int it=0; it<4; ++it){
      float v[4] = {pa[it].x, pa[it].y, pa[it].z, pa[it].w};
      if (!TA){
        int id = tid + it*256, row = id>>3, c4 = id&7;
#pragma unroll
        for (int u=0;u<4;u++){ __nv_bfloat16 h,l; bsplit(v[u],h,l);
          hA[row*SROW + c4*4 + u] = h; lA[row*SROW + c4*4 + u] = l; }
      } else {
        int kk = (tid>>5) + it*8, m4 = tid&31;
#pragma unroll
        for (int u=0;u<4;u++){ __nv_bfloat16 h,l; bsplit(v[u],h,l);
          hA[(m4*4+u)*SROW + kk] = h; lA[(m4*4+u)*SROW + kk] = l; }
      }
    }
#pragma unroll
    for (int it=0; it<4; ++it){
      float v[4] = {pb[it].x, pb[it].y, pb[it].z, pb[it].w};
      if (!TB){
        int id = tid + it*256, row = id>>3, c4 = id&7;
#pragma unroll
        for (int u=0;u<4;u++){ __nv_bfloat16 h,l; bsplit(v[u],h,l);
          hB[row*SROW + c4*4 + u] = h; lB[row*SROW + c4*4 + u] = l; }
      } else {
        int kk = (tid>>5) + it*8, n4 = tid&31;
#pragma unroll
        for (int u=0;u<4;u++){ __nv_bfloat16 h,l; bsplit(v[u],h,l);
          hB[(n4*4+u)*SROW + kk] = h; lB[(n4*4+u)*SROW + kk] = l; }
      }
    }
  };

  loadA(0); loadB(0); stsAll(0);
  __syncthreads();

  const int warp = tid>>5, lane = tid&31;
  const int wm = (warp>>1)*32, wn = (warp&1)*64;
  const int r = lane>>2, c2 = (lane&3)*2;

  for (int kt=0; kt<nK; ++kt){
    int nxt = kt+1;
    if (nxt < nK){ loadA(nxt*BK); loadB(nxt*BK); }
    {
      const __nv_bfloat16* hA = sbase + (kt&1)*4*TILEH;
      const __nv_bfloat16* lA = hA + TILEH;
      const __nv_bfloat16* hB = lA + TILEH;
      const __nv_bfloat16* lB = hB + TILEH;
#pragma unroll
      for (int s=0;s<2;s++){
        uint32_t ah[2][4], al[2][4];
        int cc = c2 + s*16;
#pragma unroll
        for (int mt=0;mt<2;mt++){
          int rr = wm + mt*16 + r;
          ah[mt][0] = *(const uint32_t*)(hA + rr*SROW + cc);
          ah[mt][1] = *(const uint32_t*)(hA + (rr+8)*SROW + cc);
          ah[mt][2] = *(const uint32_t*)(hA + rr*SROW + cc + 8);
          ah[mt][3] = *(const uint32_t*)(hA + (rr+8)*SROW + cc + 8);
          al[mt][0] = *(const uint32_t*)(lA + rr*SROW + cc);
          al[mt][1] = *(const uint32_t*)(lA + (rr+8)*SROW + cc);
          al[mt][2] = *(const uint32_t*)(lA + rr*SROW + cc + 8);
          al[mt][3] = *(const uint32_t*)(lA + (rr+8)*SROW + cc + 8);
        }
#pragma unroll
        for (int nt=0;nt<8;nt++){
          int bn = wn + nt*8 + r;
          uint32_t bh[2], bl[2];
          bh[0] = *(const uint32_t*)(hB + bn*SROW + cc);
          bh[1] = *(const uint32_t*)(hB + bn*SROW + cc + 8);
          bl[0] = *(const uint32_t*)(lB + bn*SROW + cc);
          bl[1] = *(const uint32_t*)(lB + bn*SROW + cc + 8);
#pragma unroll
          for (int mt=0;mt<2;mt++){
            mma_bf16(acc[mt][nt], ah[mt], bh);
            mma_bf16(acc[mt][nt], ah[mt], bl);
            mma_bf16(acc[mt][nt], al[mt], bh);
          }
        }
      }
    }
    if (nxt < nK) stsAll(nxt&1);
    __syncthreads();
  }

#pragma unroll
  for (int mt=0;mt<2;mt++){
#pragma unroll
    for (int nt=0;nt<8;nt++){
      int row = mBase + wm + mt*16 + r;
      int col = nBase + wn + nt*8 + c2;
      emit_one<EPI>(C, row,   col,   N, acc[mt][nt][0], bias, X2);
      emit_one<EPI>(C, row,   col+1, N, acc[mt][nt][1], bias, X2);
      emit_one<EPI>(C, row+8, col,   N, acc[mt][nt][2], bias, X2);
      emit_one<EPI>(C, row+8, col+1, N, acc[mt][nt][3], bias, X2);
    }
  }
}

// U' rows 0..31 = Pq@Wv ; 32: u1[d]=sum_e bq[e]Wk[e,d] ; 33: u2[d]=sum_e Wq[e,d]bk[e]
__global__ __launch_bounds__(256)
void prep_k(const float* __restrict__ Pq, const float* __restrict__ Wv,
            const float* __restrict__ Wk, const float* __restrict__ Wq,
            const float* __restrict__ bq, const float* __restrict__ bk,
            const float* __restrict__ bv,
            float* __restrict__ U, float* __restrict__ pbv, float* __restrict__ c0)
{
  __shared__ float srow[DIM];
  int b = blockIdx.x, tid = threadIdx.x;
  if (b < 32){
    for (int e=tid;e<DIM;e+=256) srow[e]=Pq[b*DIM+e];
    __syncthreads();
    for (int d=tid; d<DIM; d+=256){
      float acc=0.f;
      for (int e=0;e<DIM;e++) acc += srow[e]*Wv[(size_t)e*DIM+d];
      U[(size_t)b*DIM+d]=acc;
    }
  } else if (b==32){
    for (int e=tid;e<DIM;e+=256) srow[e]=bq[e];
    __syncthreads();
    for (int d=tid; d<DIM; d+=256){
      float acc=0.f;
      for (int e=0;e<DIM;e++) acc += srow[e]*Wk[(size_t)e*DIM+d];
      U[(size_t)32*DIM+d]=acc;
    }
  } else if (b==33){
    for (int e=tid;e<DIM;e+=256) srow[e]=bk[e];
    __syncthreads();
    for (int d=tid; d<DIM; d+=256){
      float acc=0.f;
      for (int e=0;e<DIM;e++) acc += srow[e]*Wq[(size_t)e*DIM+d];
      U[(size_t)33*DIM+d]=acc;
    }
  } else if (b==34){
    int w = tid>>5, l = tid&31;
    for (int p=w; p<32; p+=8){
      float acc=0.f;
      for (int d=l; d<DIM; d+=32) acc += Pq[p*DIM+d]*bv[d];
      for (int o=16;o;o>>=1) acc += __shfl_down_sync(0xffffffffu, acc, o);
      if (l==0) pbv[p]=acc;
    }
  } else {
    __shared__ float red[256];
    float acc=0.f;
    for (int d=tid; d<DIM; d+=256) acc += bq[d]*bk[d];
    red[tid]=acc; __syncthreads();
    for (int s=128; s>0; s>>=1){ if (tid<s) red[tid]+=red[tid+s]; __syncthreads(); }
    if (tid==0) c0[0]=red[0];
  }
}

__global__ __launch_bounds__(256)
void token_k(const float* __restrict__ A, const float* __restrict__ CA,
             const float* __restrict__ GA, const float* __restrict__ CB,
             const float* __restrict__ tkw, const float* __restrict__ pbv,
             const float* __restrict__ c0p, float* __restrict__ Z)
{
  extern __shared__ float sm[];
  float* sA = sm;         // 8*1024
  float* sC = sm + 8192;  // 8*1024
  __shared__ float sGA[8][NU];
  __shared__ float sS[64];
  __shared__ float sAttn[64];
  __shared__ float sNps[32][8];
  __shared__ float sFa[8];
  __shared__ float sW[8];
  __shared__ float sScore[32];

  const int t = blockIdx.x, tid = threadIdx.x;
  const size_t base = (size_t)t*8*DIM;
  const float4* A4 = (const float4*)(A + base);
  const float4* C4 = (const float4*)(CA + base);
  float4* sA4 = (float4*)sA; float4* sC4 = (float4*)sC;
  for (int i=tid; i<2048; i+=256){ sA4[i]=A4[i]; sC4[i]=C4[i]; }
  for (int i=tid; i<8*NU; i+=256) sGA[i/NU][i%NU] = GA[(size_t)(t*8 + i/NU)*NU + i%NU];
  __syncthreads();

  int warp = tid>>5, lane = tid&31;
  for (int p8=0;p8<8;p8++){
    int pair = warp*8+p8;
    const float* ai = sA + (pair>>3)*DIM;
    const float* cj = sC + (pair&7)*DIM;
    float acc=0.f;
    for (int d=lane; d<DIM; d+=32) acc += ai[d]*cj[d];
    for (int o=16;o;o>>=1) acc += __shfl_xor_sync(0xffffffffu, acc, o);
    if (lane==0) sS[pair]=acc;
  }
  __syncthreads();

  float c0 = c0p[0];
  if (warp==0 && lane<8){
    int i=lane;
    float s[8], mx=-1e30f;
    for (int j=0;j<8;j++){ s[j]=SCL*(sS[i*8+j]+sGA[j][32]+sGA[i][33]+c0); mx=fmaxf(mx,s[j]); }
    float sum=0.f;
    for (int j=0;j<8;j++){ s[j]=expf(s[j]-mx); sum+=s[j]; }
    float inv=1.f/sum;
    for (int j=0;j<8;j++) sAttn[i*8+j]=s[j]*inv;
  }
  __syncthreads();
  if (warp==1){
    int p=lane;
    const float* w8 = tkw + (size_t)t*8;
    float nb=0.f;
    for (int i=0;i<8;i++){
      float acc=0.f;
      for (int j=0;j<8;j++) acc += sAttn[i*8+j]*sGA[j][p];
      float nps = SCL*(acc + pbv[p]);
      sNps[p][i]=nps;
      nb += nps * w8[i];
    }
    sScore[p] = 0.5f*nb + 0.5f*CB[(size_t)t*32+p];
  }
  __syncthreads();
  if (tid==0){
    int sel[4]; float sv[4];
    unsigned used=0u;
    for (int r2=0;r2<4;r2++){
      float best=-1e30f; int bi=0;
      for (int p=0;p<32;p++) if(!((used>>p)&1u) && sScore[p]>best){best=sScore[p];bi=p;}
      used |= 1u<<bi; sel[r2]=bi; sv[r2]=best;
    }
    float mx=sv[0], tw[4], sum=0.f;
    for(int r2=0;r2<4;r2++){ tw[r2]=expf(sv[r2]-mx); sum+=tw[r2]; }
    float fa[8]={0,0,0,0,0,0,0,0};
    for(int r2=0;r2<4;r2++){
      int p=sel[r2];
      float m2=-1e30f;
      for(int k=0;k<8;k++) m2=fmaxf(m2,sNps[p][k]);
      float e[8], s2=0.f;
      for(int k=0;k<8;k++){ e[k]=expf(sNps[p][k]-m2); s2+=e[k]; }
      float inv=(tw[r2]/sum)/s2;
      for(int k=0;k<8;k++) fa[k]+=e[k]*inv;
    }
    for(int k=0;k<8;k++) sFa[k]=fa[k];
  }
  __syncthreads();
  if (tid<8){
    float w=0.f;
    for(int i=0;i<8;i++) w += sFa[i]*sAttn[i*8+tid];
    sW[tid]=w;
  }
  __syncthreads();
  for (int d=tid; d<DIM; d+=256){
    float acc=0.f;
    for(int j=0;j<8;j++) acc += sW[j]*sA[j*DIM+d];
    Z[(size_t)t*DIM+d]=acc;
  }
}

extern "C" void kernel_launch(void* const* d_in, const int* in_sizes, int n_in,
                              void* d_out, int out_size) {
  const float* x    = (const float*)d_in[0];
  const float* tkw  = (const float*)d_in[3];
  const float* A    = (const float*)d_in[4];
  const float* ctx  = (const float*)d_in[5];
  const float* Wq   = (const float*)d_in[6];
  const float* bq   = (const float*)d_in[7];
  const float* Wk   = (const float*)d_in[8];
  const float* bk   = (const float*)d_in[9];
  const float* Wv   = (const float*)d_in[10];
  const float* bv   = (const float*)d_in[11];
  const float* Pq   = (const float*)d_in[12];
  const float* Wup  = (const float*)d_in[13];
  const float* bup  = (const float*)d_in[14];
  const float* Wdn  = (const float*)d_in[15];
  const float* bdn  = (const float*)d_in[16];
  float* out = (float*)d_out;

  float *pC, *pCA, *pG, *pU, *pCB, *pZ, *pCO, *pH, *ppbv, *pc0;
  cudaGetSymbolAddress((void**)&pC,  g_C);
  cudaGetSymbolAddress((void**)&pCA, g_CA);
  cudaGetSymbolAddress((void**)&pG,  g_G);
  cudaGetSymbolAddress((void**)&pU,  g_U);
  cudaGetSymbolAddress((void**)&pCB, g_CB);
  cudaGetSymbolAddress((void**)&pZ,  g_Z);
  cudaGetSymbolAddress((void**)&pCO, g_CO);
  cudaGetSymbolAddress((void**)&pH,  g_H);
  cudaGetSymbolAddress((void**)&ppbv,g_pbv);
  cudaGetSymbolAddress((void**)&pc0, g_c0);

  cudaFuncSetAttribute(gemm_k<true ,true ,0>, cudaFuncAttributeMaxDynamicSharedMemorySize, GEMM_SMEM);
  cudaFuncSetAttribute(gemm_k<false,false,0>, cudaFuncAttributeMaxDynamicSharedMemorySize, GEMM_SMEM);
  cudaFuncSetAttribute(gemm_k<false,false,1>, cudaFuncAttributeMaxDynamicSharedMemorySize, GEMM_SMEM);
  cudaFuncSetAttribute(gemm_k<false,false,2>, cudaFuncAttributeMaxDynamicSharedMemorySize, GEMM_SMEM);
  cudaFuncSetAttribute(gemm_k<false,false,3>, cudaFuncAttributeMaxDynamicSharedMemorySize, GEMM_SMEM);
  cudaFuncSetAttribute(token_k, cudaFuncAttributeMaxDynamicSharedMemorySize, 65536);

  prep_k<<<36,256>>>(Pq, Wv, Wk, Wq, bq, bk, bv, pU, ppbv, pc0);
  // C = Wq^T Wk
  gemm_k<true,true,0><<<dim3(8,8),256,GEMM_SMEM>>>(Wq, Wk, pC, DIM, DIM, DIM, nullptr, nullptr);
  // CA = A @ C^T
  gemm_k<false,false,0><<<dim3(8,256),256,GEMM_SMEM>>>(A, pC, pCA, MA, DIM, DIM, nullptr, nullptr);
  // G = A @ U'^T
  gemm_k<false,false,0><<<dim3(1,256),256,GEMM_SMEM>>>(A, pU, pG, MA, NU, DIM, nullptr, nullptr);
  // CB = context @ Pq^T
  gemm_k<false,false,0><<<dim3(1,32),256,GEMM_SMEM>>>(ctx, Pq, pCB, TOK, 32, DIM, nullptr, nullptr);
  // per-token attention -> Z
  token_k<<<TOK,256,65536>>>(A, pCA, pG, pCB, tkw, ppbv, pc0, pZ);
  // combined = Z @ Wv^T + bv + x
  gemm_k<false,false,3><<<dim3(8,32),256,GEMM_SMEM>>>(pZ, Wv, pCO, TOK, DIM, DIM, bv, x);
  // H = gelu(combined @ Wup^T + bup)
  gemm_k<false,false,2><<<dim3(32,32),256,GEMM_SMEM>>>(pCO, Wup, pH, TOK, FDIM, DIM, bup, nullptr);
  // out = H @ Wdown^T + bdown
  gemm_k<false,false,1><<<dim3(8,32),256,GEMM_SMEM>>>(pH, Wdn, out, TOK, DIM, FDIM, bdn, nullptr);
}